// round 13
// baseline (speedup 1.0000x reference)
#include <cuda_runtime.h>
#include <cuda_bf16.h>

// Problem constants (fixed by the dataset)
#define MAX_N 10000
#define DIM   256
// groups of 128 columns, 4 x uint32 per group
#define MAX_GRP ((MAX_N + 127) / 128)        // 79
#define MAX_WPG (MAX_GRP * 4)                // 316 uint32 words per row
#define ROWS_PER_BLOCK 4

// Scratch (device globals; no allocation allowed)
__device__ unsigned g_bits32[(long)MAX_N * MAX_WPG]; // packed adj1, 12.64 MB
__device__ float g_y2[MAX_N];
__device__ unsigned char g_flags[MAX_N];

// ---------------------------------------------------------------------------
// Flag kernel: mark nodes that appear in tar_ei (rows we must pack).
// ---------------------------------------------------------------------------
__global__ void flag_kernel(const int* __restrict__ tar, int cnt,
                            unsigned char* __restrict__ flags) {
    int i = blockIdx.x * blockDim.x + threadIdx.x;
    if (i < cnt) flags[tar[i]] = 1;
}

// ---------------------------------------------------------------------------
// node_y2: y2[n] = x[n].W2  (y1 is folded into edge_dot).
// Launched PSS after pack (pack triggers at block start): executes under
// pack's last wave; only edge_cn (plain launch) consumes y2.
// ---------------------------------------------------------------------------
__global__ void node_y2_kernel(const float* __restrict__ x,
                               const float* __restrict__ W,   // [1, 3*DIM]
                               int n,
                               float* __restrict__ y2) {
    int warp = (blockIdx.x * blockDim.x + threadIdx.x) >> 5;
    int lane = threadIdx.x & 31;
    if (warp >= n) return;
    const float4* xr = (const float4*)(x + (long)warp * DIM);
    const float4* w2 = (const float4*)(W + 2 * DIM);
    float s2 = 0.f;
#pragma unroll
    for (int k = 0; k < 2; k++) {
        int i = lane * 2 + k;                  // 64 float4 per row
        float4 xv = xr[i];
        float4 b  = w2[i];
        s2 += xv.x * b.x + xv.y * b.y + xv.z * b.z + xv.w * b.w;
    }
#pragma unroll
    for (int o = 16; o; o >>= 1)
        s2 += __shfl_xor_sync(0xFFFFFFFFu, s2, o);
    if (lane == 0) y2[warp] = s2;
}

// ---------------------------------------------------------------------------
// edge_dot: out[e] = xij.W0 + cn0 corrections + bias.
// y1 terms (x[ti].W1, x[tj].W1) computed INLINE from the already-loaded x
// rows. Triggers PDL at start; fully overlapped with pack.
// ---------------------------------------------------------------------------
__global__ void edge_dot_kernel(const float* __restrict__ x,
                                const int* __restrict__ tar,   // [2, E]
                                const float* __restrict__ W,   // [1, 3*DIM]
                                const float* __restrict__ bxs,
                                const unsigned* __restrict__ adj, // raw adj1
                                int n, int e_cnt,
                                float* __restrict__ out) {
    cudaTriggerProgrammaticLaunchCompletion();
    int warp = (blockIdx.x * blockDim.x + threadIdx.x) >> 5;
    int lane = threadIdx.x & 31;
    if (warp >= e_cnt) return;

    int ti = tar[warp];
    int tj = tar[e_cnt + warp];

    // cn0 correction bits straight from the raw bool matrix (rare-taken).
    unsigned aii = 0, ajj = 0, aij = 0, aji = 0;
    if (lane == 0) {
        aii = adj[(long)ti * n + ti];
        aji = adj[(long)tj * n + ti];
        aij = adj[(long)ti * n + tj];
        ajj = adj[(long)tj * n + tj];
    }

    const float4* xi = (const float4*)(x + (long)ti * DIM);
    const float4* xj = (const float4*)(x + (long)tj * DIM);
    const float4* w0 = (const float4*)W;
    const float4* w1 = (const float4*)(W + DIM);
    float s = 0.f, s1i = 0.f, s1j = 0.f;
#pragma unroll
    for (int k = 0; k < 2; k++) {
        int i = lane * 2 + k;
        float4 a  = xi[i];
        float4 b4 = xj[i];
        float4 w  = w0[i];
        float4 v  = w1[i];
        s   += a.x * b4.x * w.x + a.y * b4.y * w.y
             + a.z * b4.z * w.z + a.w * b4.w * w.w;
        s1i += a.x * v.x + a.y * v.y + a.z * v.z + a.w * v.w;
        s1j += b4.x * v.x + b4.y * v.y + b4.z * v.z + b4.w * v.w;
    }
#pragma unroll
    for (int o = 16; o; o >>= 1) {
        s   += __shfl_xor_sync(0xFFFFFFFFu, s, o);
        s1i += __shfl_xor_sync(0xFFFFFFFFu, s1i, o);
        s1j += __shfl_xor_sync(0xFFFFFFFFu, s1j, o);
    }

    if (lane == 0) {
        float s0 = 0.f;
        if (ti == tj) {
            if (!aii) s0 = s1i;
        } else {
            if (aji && !aii) s0 += s1i;
            if (aij && !ajj) s0 += s1j;
        }
        out[warp] = s + s0 + bxs[0];
    }
}

// ---------------------------------------------------------------------------
// pack: FOUR rows per block, FLATTENED work loop.
// A small shared list holds the block's flagged rows (compacts flag holes
// out of the warp loop). One flat loop over count*19 quads striped across
// 8 warps -> max/mean warp work 10/9.5 (5% slack) vs 3/2.375 (26%) before.
// Quad body is the proven MLP=4 core: FOUR independent uint4 streaming
// loads, 16 ballots, 4 parallel stores from lanes 0..3.
// Bit layout: word = group*4 + k; bit 'lane' = column group*128 + lane*4 + k.
// Triggers PDL at block START (node_y2 PSS starts under pack's last wave).
// ---------------------------------------------------------------------------
__global__ void pack_adj_kernel(const unsigned int* __restrict__ adj,
                                const unsigned char* __restrict__ flags,
                                int n, int ngroups,
                                unsigned* __restrict__ bits) {
    cudaTriggerProgrammaticLaunchCompletion();

    __shared__ int s_rows[ROWS_PER_BLOCK];
    __shared__ int s_cnt;

    int row0 = blockIdx.x * ROWS_PER_BLOCK;
    if (threadIdx.x == 0) {
        int c = 0;
#pragma unroll
        for (int k = 0; k < ROWS_PER_BLOCK; k++) {
            int r = row0 + k;
            if (r < n && flags[r]) s_rows[c++] = r;
        }
        s_cnt = c;
    }
    __syncthreads();
    int cnt = s_cnt;
    if (cnt == 0) return;

    int warp = threadIdx.x >> 5;
    int lane = threadIdx.x & 31;
    int nwarps = blockDim.x >> 5;
    int nquads = ngroups >> 2;                 // 19 (groups 0..75 full)

    // Flat quad loop over all flagged rows in this block.
    int total = cnt * nquads;
    for (int t = warp; t < total; t += nwarps) {
        int r = t / nquads;                    // small const-ish div
        int q = t - r * nquads;
        int row = s_rows[r];
        const uint4* rowp4 = (const uint4*)(adj + (long)row * n);
        uint4* outp = (uint4*)(bits + (long)row * (ngroups * 4));

        int g0 = q * 4;
        uint4 v0 = __ldcs(&rowp4[(g0 + 0) * 32 + lane]);
        uint4 v1 = __ldcs(&rowp4[(g0 + 1) * 32 + lane]);
        uint4 v2 = __ldcs(&rowp4[(g0 + 2) * 32 + lane]);
        uint4 v3 = __ldcs(&rowp4[(g0 + 3) * 32 + lane]);

        unsigned a0 = __ballot_sync(0xFFFFFFFFu, v0.x != 0u);
        unsigned a1 = __ballot_sync(0xFFFFFFFFu, v0.y != 0u);
        unsigned a2 = __ballot_sync(0xFFFFFFFFu, v0.z != 0u);
        unsigned a3 = __ballot_sync(0xFFFFFFFFu, v0.w != 0u);
        unsigned b0 = __ballot_sync(0xFFFFFFFFu, v1.x != 0u);
        unsigned b1 = __ballot_sync(0xFFFFFFFFu, v1.y != 0u);
        unsigned b2 = __ballot_sync(0xFFFFFFFFu, v1.z != 0u);
        unsigned b3 = __ballot_sync(0xFFFFFFFFu, v1.w != 0u);
        unsigned c0 = __ballot_sync(0xFFFFFFFFu, v2.x != 0u);
        unsigned c1 = __ballot_sync(0xFFFFFFFFu, v2.y != 0u);
        unsigned c2 = __ballot_sync(0xFFFFFFFFu, v2.z != 0u);
        unsigned c3 = __ballot_sync(0xFFFFFFFFu, v2.w != 0u);
        unsigned d0 = __ballot_sync(0xFFFFFFFFu, v3.x != 0u);
        unsigned d1 = __ballot_sync(0xFFFFFFFFu, v3.y != 0u);
        unsigned d2 = __ballot_sync(0xFFFFFFFFu, v3.z != 0u);
        unsigned d3 = __ballot_sync(0xFFFFFFFFu, v3.w != 0u);

        if (lane == 0)      outp[g0]     = make_uint4(a0, a1, a2, a3);
        else if (lane == 1) outp[g0 + 1] = make_uint4(b0, b1, b2, b3);
        else if (lane == 2) outp[g0 + 2] = make_uint4(c0, c1, c2, c3);
        else if (lane == 3) outp[g0 + 3] = make_uint4(d0, d1, d2, d3);
    }

    // Flat tail loop: (ngroups - nquads*4) groups per row (76..78), bounds-
    // checked single-group body.
    int ntail = ngroups - nquads * 4;          // 3
    int ttotal = cnt * ntail;
    for (int t = warp; t < ttotal; t += nwarps) {
        int r = t / ntail;
        int gi = t - r * ntail;
        int row = s_rows[r];
        const uint4* rowp4 = (const uint4*)(adj + (long)row * n);
        uint4* outp = (uint4*)(bits + (long)row * (ngroups * 4));
        int tg = nquads * 4 + gi;

        int col0 = tg * 128 + lane * 4;
        uint4 v = make_uint4(0u, 0u, 0u, 0u);
        if (col0 + 3 < n) {
            v = __ldcs(&rowp4[tg * 32 + lane]);
        } else if (col0 < n) {
            const unsigned* p = adj + (long)row * n + col0;
            v.x = p[0];
            if (col0 + 1 < n) v.y = p[1];
            if (col0 + 2 < n) v.z = p[2];
        }
        unsigned b0 = __ballot_sync(0xFFFFFFFFu, v.x != 0u);
        unsigned b1 = __ballot_sync(0xFFFFFFFFu, v.y != 0u);
        unsigned b2 = __ballot_sync(0xFFFFFFFFu, v.z != 0u);
        unsigned b3 = __ballot_sync(0xFFFFFFFFu, v.w != 0u);
        if (lane == 0)
            outp[tg] = make_uint4(b0, b1, b2, b3);
    }
}

// ---------------------------------------------------------------------------
// edge_cn: out[e] += sum_{n in cn1(e)} y2[n].  PLAIN launch (waits pack +
// node_y2). All 6 uint4 L2 loads front-batched (one L2 round-trip deep).
// ---------------------------------------------------------------------------
__global__ void edge_cn_kernel(const int* __restrict__ tar,   // [2, E]
                               int e_cnt, int ngroups,
                               const unsigned* __restrict__ bits,
                               const float* __restrict__ y2,
                               float* __restrict__ out) {
    int warp = (blockIdx.x * blockDim.x + threadIdx.x) >> 5;
    int lane = threadIdx.x & 31;
    if (warp >= e_cnt) return;

    int ti = tar[warp];
    int tj = tar[e_cnt + warp];
    int wpg = ngroups * 4;

    const uint4* A = (const uint4*)(bits + (long)ti * wpg);
    const uint4* B = (const uint4*)(bits + (long)tj * wpg);

    // Front-batched loads: slots g, g+32, g+64 (assumes ngroups <= 96).
    int g0 = lane, g1 = lane + 32, g2 = lane + 64;
    uint4 z = make_uint4(0u, 0u, 0u, 0u);
    uint4 a0 = z, b0 = z, a1 = z, b1 = z, a2 = z, b2 = z;
    if (g0 < ngroups) { a0 = A[g0]; b0 = B[g0]; }
    if (g1 < ngroups) { a1 = A[g1]; b1 = B[g1]; }
    if (g2 < ngroups) { a2 = A[g2]; b2 = B[g2]; }

    float s = 0.f;
    {
        unsigned m0 = a0.x & b0.x, m1 = a0.y & b0.y;
        unsigned m2 = a0.z & b0.z, m3 = a0.w & b0.w;
        int base = g0 * 128;
        while (m0) { int bb = __ffs(m0) - 1; m0 &= m0 - 1; s += y2[base + bb * 4 + 0]; }
        while (m1) { int bb = __ffs(m1) - 1; m1 &= m1 - 1; s += y2[base + bb * 4 + 1]; }
        while (m2) { int bb = __ffs(m2) - 1; m2 &= m2 - 1; s += y2[base + bb * 4 + 2]; }
        while (m3) { int bb = __ffs(m3) - 1; m3 &= m3 - 1; s += y2[base + bb * 4 + 3]; }
    }
    {
        unsigned m0 = a1.x & b1.x, m1 = a1.y & b1.y;
        unsigned m2 = a1.z & b1.z, m3 = a1.w & b1.w;
        int base = g1 * 128;
        while (m0) { int bb = __ffs(m0) - 1; m0 &= m0 - 1; s += y2[base + bb * 4 + 0]; }
        while (m1) { int bb = __ffs(m1) - 1; m1 &= m1 - 1; s += y2[base + bb * 4 + 1]; }
        while (m2) { int bb = __ffs(m2) - 1; m2 &= m2 - 1; s += y2[base + bb * 4 + 2]; }
        while (m3) { int bb = __ffs(m3) - 1; m3 &= m3 - 1; s += y2[base + bb * 4 + 3]; }
    }
    {
        unsigned m0 = a2.x & b2.x, m1 = a2.y & b2.y;
        unsigned m2 = a2.z & b2.z, m3 = a2.w & b2.w;
        int base = g2 * 128;
        while (m0) { int bb = __ffs(m0) - 1; m0 &= m0 - 1; s += y2[base + bb * 4 + 0]; }
        while (m1) { int bb = __ffs(m1) - 1; m1 &= m1 - 1; s += y2[base + bb * 4 + 1]; }
        while (m2) { int bb = __ffs(m2) - 1; m2 &= m2 - 1; s += y2[base + bb * 4 + 2]; }
        while (m3) { int bb = __ffs(m3) - 1; m3 &= m3 - 1; s += y2[base + bb * 4 + 3]; }
    }

#pragma unroll
    for (int o = 16; o; o >>= 1)
        s += __shfl_xor_sync(0xFFFFFFFFu, s, o);

    if (lane == 0 && s != 0.f)
        out[warp] += s;
}

// ---------------------------------------------------------------------------
// Launch
// Inputs (metadata order): x[N*D] f32, adj01[N*N], adj1[N*N], tar_ei[2*E] i32,
//                          Wxs[1*3D] f32, bxs[1] f32, NCN_mode i32 (==0)
// Output: [E, 1] f32
// Stream/PDL order:
//   memset(flags) -> flag -> edge_dot (plain, trigger@start)
//   -> pack   (PSS: starts right after edge_dot's single wave launches)
//   -> node_y2(PSS: starts under pack's last wave; pack triggers at start)
//   -> edge_cn(plain: waits pack + node_y2 completion)
// ---------------------------------------------------------------------------
extern "C" void kernel_launch(void* const* d_in, const int* in_sizes, int n_in,
                              void* d_out, int out_size) {
    const float*        x    = (const float*)d_in[0];
    const unsigned int* adj1 = (const unsigned int*)d_in[2];  // bool as 4-byte words
    const int*          tar  = (const int*)d_in[3];
    const float*        Wxs  = (const float*)d_in[4];
    const float*        bxs  = (const float*)d_in[5];
    float*              out  = (float*)d_out;

    const int N = in_sizes[0] / DIM;            // 10000
    const int E = in_sizes[3] / 2;              // 8192
    const int NGRP = (N + 127) / 128;           // 79

    unsigned* bits;
    float* y2;
    unsigned char* flags;
    cudaGetSymbolAddress((void**)&bits, g_bits32);
    cudaGetSymbolAddress((void**)&y2, g_y2);
    cudaGetSymbolAddress((void**)&flags, g_flags);

    // Flags: zero (10 KB) then scatter-mark rows referenced by tar_ei
    cudaMemsetAsync(flags, 0, (size_t)N);
    flag_kernel<<<(2 * E + 255) / 256, 256>>>(tar, 2 * E, flags);

    // edge_dot: plain launch (waits for flag), PDL trigger at block start
    edge_dot_kernel<<<(E + 7) / 8, 256>>>(x, tar, Wxs, bxs, adj1, N, E, out);

    cudaLaunchAttribute pss[1];
    pss[0].id = cudaLaunchAttributeProgrammaticStreamSerialization;
    pss[0].val.programmaticStreamSerializationAllowed = 1;

    // pack: PSS directly after edge_dot -> starts ~immediately
    {
        cudaLaunchConfig_t cfg = {};
        cfg.gridDim  = dim3((unsigned)((N + ROWS_PER_BLOCK - 1) / ROWS_PER_BLOCK));
        cfg.blockDim = dim3(256);
        cfg.attrs = pss;
        cfg.numAttrs = 1;
        cudaLaunchKernelEx(&cfg, pack_adj_kernel, adj1,
                           (const unsigned char*)flags, N, NGRP,
                           (unsigned*)bits);
    }

    // node_y2: PSS after pack (pack triggers at block start) -> executes
    // under pack's last wave; finishes before pack completes.
    {
        cudaLaunchConfig_t cfg = {};
        cfg.gridDim  = dim3((N + 7) / 8);
        cfg.blockDim = dim3(256);
        cfg.attrs = pss;
        cfg.numAttrs = 1;
        cudaLaunchKernelEx(&cfg, node_y2_kernel, x, Wxs, N, y2);
    }

    // edge_cn: plain launch -> waits for pack + node_y2 completion
    edge_cn_kernel<<<(E + 7) / 8, 256>>>(tar, E, NGRP, bits, y2, out);

    (void)n_in; (void)out_size;
}

// round 14
// speedup vs baseline: 1.0235x; 1.0235x over previous
#include <cuda_runtime.h>
#include <cuda_bf16.h>

// Problem constants (fixed by the dataset)
#define MAX_N 10000
#define DIM   256
// groups of 128 columns, 4 x uint32 per group
#define MAX_GRP ((MAX_N + 127) / 128)        // 79
#define MAX_WPG (MAX_GRP * 4)                // 316 uint32 words per row
#define ROWS_PER_BLOCK 4

// Scratch (device globals; no allocation allowed)
__device__ unsigned g_bits32[(long)MAX_N * MAX_WPG]; // packed adj1, 12.64 MB
__device__ float g_y2[MAX_N];
__device__ unsigned char g_flags[MAX_N];

// ---------------------------------------------------------------------------
// Flag kernel: mark nodes that appear in tar_ei (rows we must pack).
// ---------------------------------------------------------------------------
__global__ void flag_kernel(const int* __restrict__ tar, int cnt,
                            unsigned char* __restrict__ flags) {
    int i = blockIdx.x * blockDim.x + threadIdx.x;
    if (i < cnt) flags[tar[i]] = 1;
}

// ---------------------------------------------------------------------------
// node_y2: y2[n] = x[n].W2  (y1 is folded into edge_dot).
// Launched PSS after pack (pack triggers at block start): executes under
// pack's last wave; only edge_cn (plain launch) consumes y2.
// ---------------------------------------------------------------------------
__global__ void node_y2_kernel(const float* __restrict__ x,
                               const float* __restrict__ W,   // [1, 3*DIM]
                               int n,
                               float* __restrict__ y2) {
    int warp = (blockIdx.x * blockDim.x + threadIdx.x) >> 5;
    int lane = threadIdx.x & 31;
    if (warp >= n) return;
    const float4* xr = (const float4*)(x + (long)warp * DIM);
    const float4* w2 = (const float4*)(W + 2 * DIM);
    float s2 = 0.f;
#pragma unroll
    for (int k = 0; k < 2; k++) {
        int i = lane * 2 + k;                  // 64 float4 per row
        float4 xv = xr[i];
        float4 b  = w2[i];
        s2 += xv.x * b.x + xv.y * b.y + xv.z * b.z + xv.w * b.w;
    }
#pragma unroll
    for (int o = 16; o; o >>= 1)
        s2 += __shfl_xor_sync(0xFFFFFFFFu, s2, o);
    if (lane == 0) y2[warp] = s2;
}

// ---------------------------------------------------------------------------
// edge_dot: out[e] = xij.W0 + cn0 corrections + bias.
// y1 terms (x[ti].W1, x[tj].W1) computed INLINE from the already-loaded x
// rows. Triggers PDL at start; fully overlapped with pack.
// ---------------------------------------------------------------------------
__global__ void edge_dot_kernel(const float* __restrict__ x,
                                const int* __restrict__ tar,   // [2, E]
                                const float* __restrict__ W,   // [1, 3*DIM]
                                const float* __restrict__ bxs,
                                const unsigned* __restrict__ adj, // raw adj1
                                int n, int e_cnt,
                                float* __restrict__ out) {
    cudaTriggerProgrammaticLaunchCompletion();
    int warp = (blockIdx.x * blockDim.x + threadIdx.x) >> 5;
    int lane = threadIdx.x & 31;
    if (warp >= e_cnt) return;

    int ti = tar[warp];
    int tj = tar[e_cnt + warp];

    // cn0 correction bits straight from the raw bool matrix (rare-taken).
    unsigned aii = 0, ajj = 0, aij = 0, aji = 0;
    if (lane == 0) {
        aii = adj[(long)ti * n + ti];
        aji = adj[(long)tj * n + ti];
        aij = adj[(long)ti * n + tj];
        ajj = adj[(long)tj * n + tj];
    }

    const float4* xi = (const float4*)(x + (long)ti * DIM);
    const float4* xj = (const float4*)(x + (long)tj * DIM);
    const float4* w0 = (const float4*)W;
    const float4* w1 = (const float4*)(W + DIM);
    float s = 0.f, s1i = 0.f, s1j = 0.f;
#pragma unroll
    for (int k = 0; k < 2; k++) {
        int i = lane * 2 + k;
        float4 a  = xi[i];
        float4 b4 = xj[i];
        float4 w  = w0[i];
        float4 v  = w1[i];
        s   += a.x * b4.x * w.x + a.y * b4.y * w.y
             + a.z * b4.z * w.z + a.w * b4.w * w.w;
        s1i += a.x * v.x + a.y * v.y + a.z * v.z + a.w * v.w;
        s1j += b4.x * v.x + b4.y * v.y + b4.z * v.z + b4.w * v.w;
    }
#pragma unroll
    for (int o = 16; o; o >>= 1) {
        s   += __shfl_xor_sync(0xFFFFFFFFu, s, o);
        s1i += __shfl_xor_sync(0xFFFFFFFFu, s1i, o);
        s1j += __shfl_xor_sync(0xFFFFFFFFu, s1j, o);
    }

    if (lane == 0) {
        float s0 = 0.f;
        if (ti == tj) {
            if (!aii) s0 = s1i;
        } else {
            if (aji && !aii) s0 += s1i;
            if (aij && !ajj) s0 += s1j;
        }
        out[warp] = s + s0 + bxs[0];
    }
}

// ---------------------------------------------------------------------------
// pack: FOUR rows per block, FLATTENED work loop.
// A small shared list holds the block's flagged rows (compacts flag holes
// out of the warp loop). One flat loop over count*19 quads striped across
// 8 warps -> max/mean warp work 10/9.5 (5% slack) vs 3/2.375 (26%) before.
// Quad body is the proven MLP=4 core: FOUR independent uint4 streaming
// loads, 16 ballots, 4 parallel stores from lanes 0..3.
// Bit layout: word = group*4 + k; bit 'lane' = column group*128 + lane*4 + k.
// Triggers PDL at block START (node_y2 PSS starts under pack's last wave).
// ---------------------------------------------------------------------------
__global__ void pack_adj_kernel(const unsigned int* __restrict__ adj,
                                const unsigned char* __restrict__ flags,
                                int n, int ngroups,
                                unsigned* __restrict__ bits) {
    cudaTriggerProgrammaticLaunchCompletion();

    __shared__ int s_rows[ROWS_PER_BLOCK];
    __shared__ int s_cnt;

    int row0 = blockIdx.x * ROWS_PER_BLOCK;
    if (threadIdx.x == 0) {
        int c = 0;
#pragma unroll
        for (int k = 0; k < ROWS_PER_BLOCK; k++) {
            int r = row0 + k;
            if (r < n && flags[r]) s_rows[c++] = r;
        }
        s_cnt = c;
    }
    __syncthreads();
    int cnt = s_cnt;
    if (cnt == 0) return;

    int warp = threadIdx.x >> 5;
    int lane = threadIdx.x & 31;
    int nwarps = blockDim.x >> 5;
    int nquads = ngroups >> 2;                 // 19 (groups 0..75 full)

    // Flat quad loop over all flagged rows in this block.
    int total = cnt * nquads;
    for (int t = warp; t < total; t += nwarps) {
        int r = t / nquads;                    // small const-ish div
        int q = t - r * nquads;
        int row = s_rows[r];
        const uint4* rowp4 = (const uint4*)(adj + (long)row * n);
        uint4* outp = (uint4*)(bits + (long)row * (ngroups * 4));

        int g0 = q * 4;
        uint4 v0 = __ldcs(&rowp4[(g0 + 0) * 32 + lane]);
        uint4 v1 = __ldcs(&rowp4[(g0 + 1) * 32 + lane]);
        uint4 v2 = __ldcs(&rowp4[(g0 + 2) * 32 + lane]);
        uint4 v3 = __ldcs(&rowp4[(g0 + 3) * 32 + lane]);

        unsigned a0 = __ballot_sync(0xFFFFFFFFu, v0.x != 0u);
        unsigned a1 = __ballot_sync(0xFFFFFFFFu, v0.y != 0u);
        unsigned a2 = __ballot_sync(0xFFFFFFFFu, v0.z != 0u);
        unsigned a3 = __ballot_sync(0xFFFFFFFFu, v0.w != 0u);
        unsigned b0 = __ballot_sync(0xFFFFFFFFu, v1.x != 0u);
        unsigned b1 = __ballot_sync(0xFFFFFFFFu, v1.y != 0u);
        unsigned b2 = __ballot_sync(0xFFFFFFFFu, v1.z != 0u);
        unsigned b3 = __ballot_sync(0xFFFFFFFFu, v1.w != 0u);
        unsigned c0 = __ballot_sync(0xFFFFFFFFu, v2.x != 0u);
        unsigned c1 = __ballot_sync(0xFFFFFFFFu, v2.y != 0u);
        unsigned c2 = __ballot_sync(0xFFFFFFFFu, v2.z != 0u);
        unsigned c3 = __ballot_sync(0xFFFFFFFFu, v2.w != 0u);
        unsigned d0 = __ballot_sync(0xFFFFFFFFu, v3.x != 0u);
        unsigned d1 = __ballot_sync(0xFFFFFFFFu, v3.y != 0u);
        unsigned d2 = __ballot_sync(0xFFFFFFFFu, v3.z != 0u);
        unsigned d3 = __ballot_sync(0xFFFFFFFFu, v3.w != 0u);

        if (lane == 0)      outp[g0]     = make_uint4(a0, a1, a2, a3);
        else if (lane == 1) outp[g0 + 1] = make_uint4(b0, b1, b2, b3);
        else if (lane == 2) outp[g0 + 2] = make_uint4(c0, c1, c2, c3);
        else if (lane == 3) outp[g0 + 3] = make_uint4(d0, d1, d2, d3);
    }

    // Flat tail loop: (ngroups - nquads*4) groups per row (76..78), bounds-
    // checked single-group body.
    int ntail = ngroups - nquads * 4;          // 3
    int ttotal = cnt * ntail;
    for (int t = warp; t < ttotal; t += nwarps) {
        int r = t / ntail;
        int gi = t - r * ntail;
        int row = s_rows[r];
        const uint4* rowp4 = (const uint4*)(adj + (long)row * n);
        uint4* outp = (uint4*)(bits + (long)row * (ngroups * 4));
        int tg = nquads * 4 + gi;

        int col0 = tg * 128 + lane * 4;
        uint4 v = make_uint4(0u, 0u, 0u, 0u);
        if (col0 + 3 < n) {
            v = __ldcs(&rowp4[tg * 32 + lane]);
        } else if (col0 < n) {
            const unsigned* p = adj + (long)row * n + col0;
            v.x = p[0];
            if (col0 + 1 < n) v.y = p[1];
            if (col0 + 2 < n) v.z = p[2];
        }
        unsigned b0 = __ballot_sync(0xFFFFFFFFu, v.x != 0u);
        unsigned b1 = __ballot_sync(0xFFFFFFFFu, v.y != 0u);
        unsigned b2 = __ballot_sync(0xFFFFFFFFu, v.z != 0u);
        unsigned b3 = __ballot_sync(0xFFFFFFFFu, v.w != 0u);
        if (lane == 0)
            outp[tg] = make_uint4(b0, b1, b2, b3);
    }
}

// ---------------------------------------------------------------------------
// edge_cn: out[e] += sum_{n in cn1(e)} y2[n].  PLAIN launch (waits pack +
// node_y2). All 6 uint4 L2 loads front-batched (one L2 round-trip deep).
// ---------------------------------------------------------------------------
__global__ void edge_cn_kernel(const int* __restrict__ tar,   // [2, E]
                               int e_cnt, int ngroups,
                               const unsigned* __restrict__ bits,
                               const float* __restrict__ y2,
                               float* __restrict__ out) {
    int warp = (blockIdx.x * blockDim.x + threadIdx.x) >> 5;
    int lane = threadIdx.x & 31;
    if (warp >= e_cnt) return;

    int ti = tar[warp];
    int tj = tar[e_cnt + warp];
    int wpg = ngroups * 4;

    const uint4* A = (const uint4*)(bits + (long)ti * wpg);
    const uint4* B = (const uint4*)(bits + (long)tj * wpg);

    // Front-batched loads: slots g, g+32, g+64 (assumes ngroups <= 96).
    int g0 = lane, g1 = lane + 32, g2 = lane + 64;
    uint4 z = make_uint4(0u, 0u, 0u, 0u);
    uint4 a0 = z, b0 = z, a1 = z, b1 = z, a2 = z, b2 = z;
    if (g0 < ngroups) { a0 = A[g0]; b0 = B[g0]; }
    if (g1 < ngroups) { a1 = A[g1]; b1 = B[g1]; }
    if (g2 < ngroups) { a2 = A[g2]; b2 = B[g2]; }

    float s = 0.f;
    {
        unsigned m0 = a0.x & b0.x, m1 = a0.y & b0.y;
        unsigned m2 = a0.z & b0.z, m3 = a0.w & b0.w;
        int base = g0 * 128;
        while (m0) { int bb = __ffs(m0) - 1; m0 &= m0 - 1; s += y2[base + bb * 4 + 0]; }
        while (m1) { int bb = __ffs(m1) - 1; m1 &= m1 - 1; s += y2[base + bb * 4 + 1]; }
        while (m2) { int bb = __ffs(m2) - 1; m2 &= m2 - 1; s += y2[base + bb * 4 + 2]; }
        while (m3) { int bb = __ffs(m3) - 1; m3 &= m3 - 1; s += y2[base + bb * 4 + 3]; }
    }
    {
        unsigned m0 = a1.x & b1.x, m1 = a1.y & b1.y;
        unsigned m2 = a1.z & b1.z, m3 = a1.w & b1.w;
        int base = g1 * 128;
        while (m0) { int bb = __ffs(m0) - 1; m0 &= m0 - 1; s += y2[base + bb * 4 + 0]; }
        while (m1) { int bb = __ffs(m1) - 1; m1 &= m1 - 1; s += y2[base + bb * 4 + 1]; }
        while (m2) { int bb = __ffs(m2) - 1; m2 &= m2 - 1; s += y2[base + bb * 4 + 2]; }
        while (m3) { int bb = __ffs(m3) - 1; m3 &= m3 - 1; s += y2[base + bb * 4 + 3]; }
    }
    {
        unsigned m0 = a2.x & b2.x, m1 = a2.y & b2.y;
        unsigned m2 = a2.z & b2.z, m3 = a2.w & b2.w;
        int base = g2 * 128;
        while (m0) { int bb = __ffs(m0) - 1; m0 &= m0 - 1; s += y2[base + bb * 4 + 0]; }
        while (m1) { int bb = __ffs(m1) - 1; m1 &= m1 - 1; s += y2[base + bb * 4 + 1]; }
        while (m2) { int bb = __ffs(m2) - 1; m2 &= m2 - 1; s += y2[base + bb * 4 + 2]; }
        while (m3) { int bb = __ffs(m3) - 1; m3 &= m3 - 1; s += y2[base + bb * 4 + 3]; }
    }

#pragma unroll
    for (int o = 16; o; o >>= 1)
        s += __shfl_xor_sync(0xFFFFFFFFu, s, o);

    if (lane == 0 && s != 0.f)
        out[warp] += s;
}

// ---------------------------------------------------------------------------
// Launch
// Inputs (metadata order): x[N*D] f32, adj01[N*N], adj1[N*N], tar_ei[2*E] i32,
//                          Wxs[1*3D] f32, bxs[1] f32, NCN_mode i32 (==0)
// Output: [E, 1] f32
// Stream/PDL order:
//   memset(flags) -> flag -> edge_dot (plain, trigger@start)
//   -> pack   (PSS: starts right after edge_dot's single wave launches)
//   -> node_y2(PSS: starts under pack's last wave; pack triggers at start)
//   -> edge_cn(plain: waits pack + node_y2 completion)
// ---------------------------------------------------------------------------
extern "C" void kernel_launch(void* const* d_in, const int* in_sizes, int n_in,
                              void* d_out, int out_size) {
    const float*        x    = (const float*)d_in[0];
    const unsigned int* adj1 = (const unsigned int*)d_in[2];  // bool as 4-byte words
    const int*          tar  = (const int*)d_in[3];
    const float*        Wxs  = (const float*)d_in[4];
    const float*        bxs  = (const float*)d_in[5];
    float*              out  = (float*)d_out;

    const int N = in_sizes[0] / DIM;            // 10000
    const int E = in_sizes[3] / 2;              // 8192
    const int NGRP = (N + 127) / 128;           // 79

    unsigned* bits;
    float* y2;
    unsigned char* flags;
    cudaGetSymbolAddress((void**)&bits, g_bits32);
    cudaGetSymbolAddress((void**)&y2, g_y2);
    cudaGetSymbolAddress((void**)&flags, g_flags);

    // Flags: zero (10 KB) then scatter-mark rows referenced by tar_ei
    cudaMemsetAsync(flags, 0, (size_t)N);
    flag_kernel<<<(2 * E + 255) / 256, 256>>>(tar, 2 * E, flags);

    // edge_dot: plain launch (waits for flag), PDL trigger at block start
    edge_dot_kernel<<<(E + 7) / 8, 256>>>(x, tar, Wxs, bxs, adj1, N, E, out);

    cudaLaunchAttribute pss[1];
    pss[0].id = cudaLaunchAttributeProgrammaticStreamSerialization;
    pss[0].val.programmaticStreamSerializationAllowed = 1;

    // pack: PSS directly after edge_dot -> starts ~immediately
    {
        cudaLaunchConfig_t cfg = {};
        cfg.gridDim  = dim3((unsigned)((N + ROWS_PER_BLOCK - 1) / ROWS_PER_BLOCK));
        cfg.blockDim = dim3(256);
        cfg.attrs = pss;
        cfg.numAttrs = 1;
        cudaLaunchKernelEx(&cfg, pack_adj_kernel, adj1,
                           (const unsigned char*)flags, N, NGRP,
                           (unsigned*)bits);
    }

    // node_y2: PSS after pack (pack triggers at block start) -> executes
    // under pack's last wave; finishes before pack completes.
    {
        cudaLaunchConfig_t cfg = {};
        cfg.gridDim  = dim3((N + 7) / 8);
        cfg.blockDim = dim3(256);
        cfg.attrs = pss;
        cfg.numAttrs = 1;
        cudaLaunchKernelEx(&cfg, node_y2_kernel, x, Wxs, N, y2);
    }

    // edge_cn: plain launch -> waits for pack + node_y2 completion
    edge_cn_kernel<<<(E + 7) / 8, 256>>>(tar, E, NGRP, bits, y2, out);

    (void)n_in; (void)out_size;
}

// round 15
// speedup vs baseline: 1.0517x; 1.0275x over previous
#include <cuda_runtime.h>
#include <cuda_bf16.h>

// Problem constants (fixed by the dataset)
#define MAX_N 10000
#define DIM   256
// groups of 128 columns, 4 x uint32 per group
#define MAX_GRP ((MAX_N + 127) / 128)        // 79
#define MAX_WPG (MAX_GRP * 4)                // 316 uint32 words per row
#define MASK_WORDS ((MAX_N + 31) / 32)       // 313

// Scratch (device globals; no allocation allowed)
__device__ unsigned g_bits32[(long)MAX_N * MAX_WPG]; // packed adj1, 12.64 MB
__device__ float g_y2[MAX_N];
__device__ unsigned g_mask[MASK_WORDS];              // flagged-node bitmask

// ---------------------------------------------------------------------------
// flag1: single block fuses zeroing + marking. Smem bitmask, atomicOr,
// one global write at the end. Replaces memset + 64-block flag kernel.
// ---------------------------------------------------------------------------
__global__ void flag1_kernel(const int* __restrict__ tar, int cnt,
                             unsigned* __restrict__ mask, int nwords) {
    __shared__ unsigned sm[MASK_WORDS];
    for (int i = threadIdx.x; i < nwords; i += blockDim.x) sm[i] = 0u;
    __syncthreads();
    for (int i = threadIdx.x; i < cnt; i += blockDim.x) {
        int nd = tar[i];
        atomicOr(&sm[nd >> 5], 1u << (nd & 31));
    }
    __syncthreads();
    for (int i = threadIdx.x; i < nwords; i += blockDim.x) mask[i] = sm[i];
}

// ---------------------------------------------------------------------------
// node_y2: y2[n] = x[n].W2  (y1 is folded into edge_dot).
// Launched PSS after pack (pack triggers at block start): executes under
// pack's last wave; only edge_cn (plain launch) consumes y2.
// ---------------------------------------------------------------------------
__global__ void node_y2_kernel(const float* __restrict__ x,
                               const float* __restrict__ W,   // [1, 3*DIM]
                               int n,
                               float* __restrict__ y2) {
    int warp = (blockIdx.x * blockDim.x + threadIdx.x) >> 5;
    int lane = threadIdx.x & 31;
    if (warp >= n) return;
    const float4* xr = (const float4*)(x + (long)warp * DIM);
    const float4* w2 = (const float4*)(W + 2 * DIM);
    float s2 = 0.f;
#pragma unroll
    for (int k = 0; k < 2; k++) {
        int i = lane * 2 + k;                  // 64 float4 per row
        float4 xv = xr[i];
        float4 b  = w2[i];
        s2 += xv.x * b.x + xv.y * b.y + xv.z * b.z + xv.w * b.w;
    }
#pragma unroll
    for (int o = 16; o; o >>= 1)
        s2 += __shfl_xor_sync(0xFFFFFFFFu, s2, o);
    if (lane == 0) y2[warp] = s2;
}

// ---------------------------------------------------------------------------
// edge_dot: out[e] = xij.W0 + cn0 corrections + bias.
// y1 terms (x[ti].W1, x[tj].W1) computed INLINE from the already-loaded x
// rows. Triggers PDL at start; fully overlapped with pack.
// ---------------------------------------------------------------------------
__global__ void edge_dot_kernel(const float* __restrict__ x,
                                const int* __restrict__ tar,   // [2, E]
                                const float* __restrict__ W,   // [1, 3*DIM]
                                const float* __restrict__ bxs,
                                const unsigned* __restrict__ adj, // raw adj1
                                int n, int e_cnt,
                                float* __restrict__ out) {
    cudaTriggerProgrammaticLaunchCompletion();
    int warp = (blockIdx.x * blockDim.x + threadIdx.x) >> 5;
    int lane = threadIdx.x & 31;
    if (warp >= e_cnt) return;

    int ti = tar[warp];
    int tj = tar[e_cnt + warp];

    // cn0 correction bits straight from the raw bool matrix (rare-taken).
    unsigned aii = 0, ajj = 0, aij = 0, aji = 0;
    if (lane == 0) {
        aii = adj[(long)ti * n + ti];
        aji = adj[(long)tj * n + ti];
        aij = adj[(long)ti * n + tj];
        ajj = adj[(long)tj * n + tj];
    }

    const float4* xi = (const float4*)(x + (long)ti * DIM);
    const float4* xj = (const float4*)(x + (long)tj * DIM);
    const float4* w0 = (const float4*)W;
    const float4* w1 = (const float4*)(W + DIM);
    float s = 0.f, s1i = 0.f, s1j = 0.f;
#pragma unroll
    for (int k = 0; k < 2; k++) {
        int i = lane * 2 + k;
        float4 a  = xi[i];
        float4 b4 = xj[i];
        float4 w  = w0[i];
        float4 v  = w1[i];
        s   += a.x * b4.x * w.x + a.y * b4.y * w.y
             + a.z * b4.z * w.z + a.w * b4.w * w.w;
        s1i += a.x * v.x + a.y * v.y + a.z * v.z + a.w * v.w;
        s1j += b4.x * v.x + b4.y * v.y + b4.z * v.z + b4.w * v.w;
    }
#pragma unroll
    for (int o = 16; o; o >>= 1) {
        s   += __shfl_xor_sync(0xFFFFFFFFu, s, o);
        s1i += __shfl_xor_sync(0xFFFFFFFFu, s1i, o);
        s1j += __shfl_xor_sync(0xFFFFFFFFu, s1j, o);
    }

    if (lane == 0) {
        float s0 = 0.f;
        if (ti == tj) {
            if (!aii) s0 = s1i;
        } else {
            if (aji && !aii) s0 += s1i;
            if (aij && !ajj) s0 += s1j;
        }
        out[warp] = s + s0 + bxs[0];
    }
}

// ---------------------------------------------------------------------------
// pack: TWO rows per block, INTERLEAVED flat quad loop (no smem, no sync,
// no division). Row list built redundantly-but-uniformly in registers from
// two bitmask reads. Flat t in [0, cnt*19): r = (t>=19), q = t - (r?19:0).
// Warp work max 5 / mean 4.75 quads (5% end-of-block slack vs 26% before).
// Quad body is the proven MLP=4 core: FOUR independent uint4 streaming
// loads, 16 ballots, 4 parallel stores from lanes 0..3. Groups 0..75
// provably full for N=10000; tail groups (76..78) flat bounds-checked loop.
// Bit layout: word = group*4 + k; bit 'lane' = column group*128 + lane*4 + k.
// Triggers PDL at block START (node_y2 PSS starts under pack's last wave).
// ---------------------------------------------------------------------------
__global__ void pack_adj_kernel(const unsigned int* __restrict__ adj,
                                const unsigned* __restrict__ mask,
                                int n, int ngroups,
                                unsigned* __restrict__ bits) {
    cudaTriggerProgrammaticLaunchCompletion();

    int row0 = blockIdx.x * 2;
    int row1 = row0 + 1;
    int f0 = (mask[row0 >> 5] >> (row0 & 31)) & 1u;
    int f1 = (row1 < n) ? ((mask[row1 >> 5] >> (row1 & 31)) & 1u) : 0;

    int ra = f0 ? row0 : row1;       // first flagged row
    int rb = row1;                   // second flagged row (only if cnt==2)
    int cnt = f0 + f1;
    if (cnt == 0) return;

    int warp = threadIdx.x >> 5;
    int lane = threadIdx.x & 31;
    int nquads = ngroups >> 2;       // 19 (groups 0..75 full)

    int total = cnt * nquads;
    for (int t = warp; t < total; t += 8) {
        int r = t >= nquads;
        int q = r ? (t - nquads) : t;
        int row = r ? rb : ra;
        const uint4* rowp4 = (const uint4*)(adj + (long)row * n);
        uint4* outp = (uint4*)(bits + (long)row * (ngroups * 4));

        int g0 = q * 4;
        uint4 v0 = __ldcs(&rowp4[(g0 + 0) * 32 + lane]);
        uint4 v1 = __ldcs(&rowp4[(g0 + 1) * 32 + lane]);
        uint4 v2 = __ldcs(&rowp4[(g0 + 2) * 32 + lane]);
        uint4 v3 = __ldcs(&rowp4[(g0 + 3) * 32 + lane]);

        unsigned a0 = __ballot_sync(0xFFFFFFFFu, v0.x != 0u);
        unsigned a1 = __ballot_sync(0xFFFFFFFFu, v0.y != 0u);
        unsigned a2 = __ballot_sync(0xFFFFFFFFu, v0.z != 0u);
        unsigned a3 = __ballot_sync(0xFFFFFFFFu, v0.w != 0u);
        unsigned b0 = __ballot_sync(0xFFFFFFFFu, v1.x != 0u);
        unsigned b1 = __ballot_sync(0xFFFFFFFFu, v1.y != 0u);
        unsigned b2 = __ballot_sync(0xFFFFFFFFu, v1.z != 0u);
        unsigned b3 = __ballot_sync(0xFFFFFFFFu, v1.w != 0u);
        unsigned c0 = __ballot_sync(0xFFFFFFFFu, v2.x != 0u);
        unsigned c1 = __ballot_sync(0xFFFFFFFFu, v2.y != 0u);
        unsigned c2 = __ballot_sync(0xFFFFFFFFu, v2.z != 0u);
        unsigned c3 = __ballot_sync(0xFFFFFFFFu, v2.w != 0u);
        unsigned d0 = __ballot_sync(0xFFFFFFFFu, v3.x != 0u);
        unsigned d1 = __ballot_sync(0xFFFFFFFFu, v3.y != 0u);
        unsigned d2 = __ballot_sync(0xFFFFFFFFu, v3.z != 0u);
        unsigned d3 = __ballot_sync(0xFFFFFFFFu, v3.w != 0u);

        if (lane == 0)      outp[g0]     = make_uint4(a0, a1, a2, a3);
        else if (lane == 1) outp[g0 + 1] = make_uint4(b0, b1, b2, b3);
        else if (lane == 2) outp[g0 + 2] = make_uint4(c0, c1, c2, c3);
        else if (lane == 3) outp[g0 + 3] = make_uint4(d0, d1, d2, d3);
    }

    // tail: groups 76..78 per flagged row, flat bounds-checked loop
    int ntail = ngroups - nquads * 4;          // 3
    int ttotal = cnt * ntail;
    for (int t = warp; t < ttotal; t += 8) {
        int r = t >= ntail;
        int gi = r ? (t - ntail) : t;
        int row = r ? rb : ra;
        const uint4* rowp4 = (const uint4*)(adj + (long)row * n);
        uint4* outp = (uint4*)(bits + (long)row * (ngroups * 4));
        int tg = nquads * 4 + gi;

        int col0 = tg * 128 + lane * 4;
        uint4 v = make_uint4(0u, 0u, 0u, 0u);
        if (col0 + 3 < n) {
            v = __ldcs(&rowp4[tg * 32 + lane]);
        } else if (col0 < n) {
            const unsigned* p = adj + (long)row * n + col0;
            v.x = p[0];
            if (col0 + 1 < n) v.y = p[1];
            if (col0 + 2 < n) v.z = p[2];
        }
        unsigned b0 = __ballot_sync(0xFFFFFFFFu, v.x != 0u);
        unsigned b1 = __ballot_sync(0xFFFFFFFFu, v.y != 0u);
        unsigned b2 = __ballot_sync(0xFFFFFFFFu, v.z != 0u);
        unsigned b3 = __ballot_sync(0xFFFFFFFFu, v.w != 0u);
        if (lane == 0)
            outp[tg] = make_uint4(b0, b1, b2, b3);
    }
}

// ---------------------------------------------------------------------------
// edge_cn: out[e] += sum_{n in cn1(e)} y2[n].  PLAIN launch (waits pack +
// node_y2). All 6 uint4 L2 loads front-batched (one L2 round-trip deep).
// ---------------------------------------------------------------------------
__global__ void edge_cn_kernel(const int* __restrict__ tar,   // [2, E]
                               int e_cnt, int ngroups,
                               const unsigned* __restrict__ bits,
                               const float* __restrict__ y2,
                               float* __restrict__ out) {
    int warp = (blockIdx.x * blockDim.x + threadIdx.x) >> 5;
    int lane = threadIdx.x & 31;
    if (warp >= e_cnt) return;

    int ti = tar[warp];
    int tj = tar[e_cnt + warp];
    int wpg = ngroups * 4;

    const uint4* A = (const uint4*)(bits + (long)ti * wpg);
    const uint4* B = (const uint4*)(bits + (long)tj * wpg);

    // Front-batched loads: slots g, g+32, g+64 (assumes ngroups <= 96).
    int g0 = lane, g1 = lane + 32, g2 = lane + 64;
    uint4 z = make_uint4(0u, 0u, 0u, 0u);
    uint4 a0 = z, b0 = z, a1 = z, b1 = z, a2 = z, b2 = z;
    if (g0 < ngroups) { a0 = A[g0]; b0 = B[g0]; }
    if (g1 < ngroups) { a1 = A[g1]; b1 = B[g1]; }
    if (g2 < ngroups) { a2 = A[g2]; b2 = B[g2]; }

    float s = 0.f;
    {
        unsigned m0 = a0.x & b0.x, m1 = a0.y & b0.y;
        unsigned m2 = a0.z & b0.z, m3 = a0.w & b0.w;
        int base = g0 * 128;
        while (m0) { int bb = __ffs(m0) - 1; m0 &= m0 - 1; s += y2[base + bb * 4 + 0]; }
        while (m1) { int bb = __ffs(m1) - 1; m1 &= m1 - 1; s += y2[base + bb * 4 + 1]; }
        while (m2) { int bb = __ffs(m2) - 1; m2 &= m2 - 1; s += y2[base + bb * 4 + 2]; }
        while (m3) { int bb = __ffs(m3) - 1; m3 &= m3 - 1; s += y2[base + bb * 4 + 3]; }
    }
    {
        unsigned m0 = a1.x & b1.x, m1 = a1.y & b1.y;
        unsigned m2 = a1.z & b1.z, m3 = a1.w & b1.w;
        int base = g1 * 128;
        while (m0) { int bb = __ffs(m0) - 1; m0 &= m0 - 1; s += y2[base + bb * 4 + 0]; }
        while (m1) { int bb = __ffs(m1) - 1; m1 &= m1 - 1; s += y2[base + bb * 4 + 1]; }
        while (m2) { int bb = __ffs(m2) - 1; m2 &= m2 - 1; s += y2[base + bb * 4 + 2]; }
        while (m3) { int bb = __ffs(m3) - 1; m3 &= m3 - 1; s += y2[base + bb * 4 + 3]; }
    }
    {
        unsigned m0 = a2.x & b2.x, m1 = a2.y & b2.y;
        unsigned m2 = a2.z & b2.z, m3 = a2.w & b2.w;
        int base = g2 * 128;
        while (m0) { int bb = __ffs(m0) - 1; m0 &= m0 - 1; s += y2[base + bb * 4 + 0]; }
        while (m1) { int bb = __ffs(m1) - 1; m1 &= m1 - 1; s += y2[base + bb * 4 + 1]; }
        while (m2) { int bb = __ffs(m2) - 1; m2 &= m2 - 1; s += y2[base + bb * 4 + 2]; }
        while (m3) { int bb = __ffs(m3) - 1; m3 &= m3 - 1; s += y2[base + bb * 4 + 3]; }
    }

#pragma unroll
    for (int o = 16; o; o >>= 1)
        s += __shfl_xor_sync(0xFFFFFFFFu, s, o);

    if (lane == 0 && s != 0.f)
        out[warp] += s;
}

// ---------------------------------------------------------------------------
// Launch
// Inputs (metadata order): x[N*D] f32, adj01[N*N], adj1[N*N], tar_ei[2*E] i32,
//                          Wxs[1*3D] f32, bxs[1] f32, NCN_mode i32 (==0)
// Output: [E, 1] f32
// Stream/PDL order:
//   flag1 (single block, fused zero+mark)
//   -> edge_dot (plain, trigger@start)
//   -> pack   (PSS: starts right after edge_dot's single wave launches)
//   -> node_y2(PSS: starts under pack's last wave; pack triggers at start)
//   -> edge_cn(plain: waits pack + node_y2 completion)
// ---------------------------------------------------------------------------
extern "C" void kernel_launch(void* const* d_in, const int* in_sizes, int n_in,
                              void* d_out, int out_size) {
    const float*        x    = (const float*)d_in[0];
    const unsigned int* adj1 = (const unsigned int*)d_in[2];  // bool as 4-byte words
    const int*          tar  = (const int*)d_in[3];
    const float*        Wxs  = (const float*)d_in[4];
    const float*        bxs  = (const float*)d_in[5];
    float*              out  = (float*)d_out;

    const int N = in_sizes[0] / DIM;            // 10000
    const int E = in_sizes[3] / 2;              // 8192
    const int NGRP = (N + 127) / 128;           // 79
    const int NWORDS = (N + 31) / 32;           // 313

    unsigned* bits;
    float* y2;
    unsigned* mask;
    cudaGetSymbolAddress((void**)&bits, g_bits32);
    cudaGetSymbolAddress((void**)&y2, g_y2);
    cudaGetSymbolAddress((void**)&mask, g_mask);

    // flag1: single block, fused zero + mark (replaces memset + flag)
    flag1_kernel<<<1, 1024>>>(tar, 2 * E, mask, NWORDS);

    // edge_dot: plain launch (waits for flag1), PDL trigger at block start
    edge_dot_kernel<<<(E + 7) / 8, 256>>>(x, tar, Wxs, bxs, adj1, N, E, out);

    cudaLaunchAttribute pss[1];
    pss[0].id = cudaLaunchAttributeProgrammaticStreamSerialization;
    pss[0].val.programmaticStreamSerializationAllowed = 1;

    // pack: PSS directly after edge_dot -> starts ~immediately
    {
        cudaLaunchConfig_t cfg = {};
        cfg.gridDim  = dim3((unsigned)((N + 1) / 2));
        cfg.blockDim = dim3(256);
        cfg.attrs = pss;
        cfg.numAttrs = 1;
        cudaLaunchKernelEx(&cfg, pack_adj_kernel, adj1,
                           (const unsigned*)mask, N, NGRP, (unsigned*)bits);
    }

    // node_y2: PSS after pack (pack triggers at block start) -> executes
    // under pack's last wave; finishes before pack completes.
    {
        cudaLaunchConfig_t cfg = {};
        cfg.gridDim  = dim3((N + 7) / 8);
        cfg.blockDim = dim3(256);
        cfg.attrs = pss;
        cfg.numAttrs = 1;
        cudaLaunchKernelEx(&cfg, node_y2_kernel, x, Wxs, N, y2);
    }

    // edge_cn: plain launch -> waits for pack + node_y2 completion
    edge_cn_kernel<<<(E + 7) / 8, 256>>>(tar, E, NGRP, bits, y2, out);

    (void)n_in; (void)out_size;
}

// round 16
// speedup vs baseline: 1.0557x; 1.0039x over previous
#include <cuda_runtime.h>
#include <cuda_bf16.h>

// Problem constants (fixed by the dataset)
#define MAX_N 10000
#define DIM   256
// groups of 128 columns, 4 x uint32 per group
#define MAX_GRP ((MAX_N + 127) / 128)        // 79
#define MAX_WPG (MAX_GRP * 4)                // 316 uint32 words per row
#define MASK_WORDS ((MAX_N + 31) / 32)       // 313

// Scratch (device globals; no allocation allowed)
__device__ unsigned g_bits32[(long)MAX_N * MAX_WPG]; // packed adj1, 12.64 MB
__device__ float g_y2[MAX_N];
__device__ unsigned g_mask[MASK_WORDS];              // flagged-node bitmask

// ---------------------------------------------------------------------------
// flag1: single block fuses zeroing + marking. Smem bitmask, atomicOr,
// one global write at the end. Launched PSS after edge_dot (which triggers
// at start) -> runs concurrent with edge_dot. Triggers PDL at the END,
// after the mask stores: pack (PSS + gridDepSync) sees the writes.
// ---------------------------------------------------------------------------
__global__ void flag1_kernel(const int* __restrict__ tar, int cnt,
                             unsigned* __restrict__ mask, int nwords) {
    __shared__ unsigned sm[MASK_WORDS];
    for (int i = threadIdx.x; i < nwords; i += blockDim.x) sm[i] = 0u;
    __syncthreads();
    for (int i = threadIdx.x; i < cnt; i += blockDim.x) {
        int nd = tar[i];
        atomicOr(&sm[nd >> 5], 1u << (nd & 31));
    }
    __syncthreads();
    for (int i = threadIdx.x; i < nwords; i += blockDim.x) mask[i] = sm[i];
    __syncthreads();
    // trigger AFTER the mask writes: dependent pack grid's
    // cudaGridDependencySynchronize() guarantees visibility.
    cudaTriggerProgrammaticLaunchCompletion();
}

// ---------------------------------------------------------------------------
// node_y2: y2[n] = x[n].W2  (y1 is folded into edge_dot).
// Launched PSS after pack (pack triggers at block start): executes under
// pack's last wave; only edge_cn (plain launch) consumes y2.
// ---------------------------------------------------------------------------
__global__ void node_y2_kernel(const float* __restrict__ x,
                               const float* __restrict__ W,   // [1, 3*DIM]
                               int n,
                               float* __restrict__ y2) {
    int warp = (blockIdx.x * blockDim.x + threadIdx.x) >> 5;
    int lane = threadIdx.x & 31;
    if (warp >= n) return;
    const float4* xr = (const float4*)(x + (long)warp * DIM);
    const float4* w2 = (const float4*)(W + 2 * DIM);
    float s2 = 0.f;
#pragma unroll
    for (int k = 0; k < 2; k++) {
        int i = lane * 2 + k;                  // 64 float4 per row
        float4 xv = xr[i];
        float4 b  = w2[i];
        s2 += xv.x * b.x + xv.y * b.y + xv.z * b.z + xv.w * b.w;
    }
#pragma unroll
    for (int o = 16; o; o >>= 1)
        s2 += __shfl_xor_sync(0xFFFFFFFFu, s2, o);
    if (lane == 0) y2[warp] = s2;
}

// ---------------------------------------------------------------------------
// edge_dot: out[e] = xij.W0 + cn0 corrections + bias.
// y1 terms (x[ti].W1, x[tj].W1) computed INLINE from the already-loaded x
// rows. Depends only on raw inputs. Triggers PDL at start.
// ---------------------------------------------------------------------------
__global__ void edge_dot_kernel(const float* __restrict__ x,
                                const int* __restrict__ tar,   // [2, E]
                                const float* __restrict__ W,   // [1, 3*DIM]
                                const float* __restrict__ bxs,
                                const unsigned* __restrict__ adj, // raw adj1
                                int n, int e_cnt,
                                float* __restrict__ out) {
    cudaTriggerProgrammaticLaunchCompletion();
    int warp = (blockIdx.x * blockDim.x + threadIdx.x) >> 5;
    int lane = threadIdx.x & 31;
    if (warp >= e_cnt) return;

    int ti = tar[warp];
    int tj = tar[e_cnt + warp];

    // cn0 correction bits straight from the raw bool matrix (rare-taken).
    unsigned aii = 0, ajj = 0, aij = 0, aji = 0;
    if (lane == 0) {
        aii = adj[(long)ti * n + ti];
        aji = adj[(long)tj * n + ti];
        aij = adj[(long)ti * n + tj];
        ajj = adj[(long)tj * n + tj];
    }

    const float4* xi = (const float4*)(x + (long)ti * DIM);
    const float4* xj = (const float4*)(x + (long)tj * DIM);
    const float4* w0 = (const float4*)W;
    const float4* w1 = (const float4*)(W + DIM);
    float s = 0.f, s1i = 0.f, s1j = 0.f;
#pragma unroll
    for (int k = 0; k < 2; k++) {
        int i = lane * 2 + k;
        float4 a  = xi[i];
        float4 b4 = xj[i];
        float4 w  = w0[i];
        float4 v  = w1[i];
        s   += a.x * b4.x * w.x + a.y * b4.y * w.y
             + a.z * b4.z * w.z + a.w * b4.w * w.w;
        s1i += a.x * v.x + a.y * v.y + a.z * v.z + a.w * v.w;
        s1j += b4.x * v.x + b4.y * v.y + b4.z * v.z + b4.w * v.w;
    }
#pragma unroll
    for (int o = 16; o; o >>= 1) {
        s   += __shfl_xor_sync(0xFFFFFFFFu, s, o);
        s1i += __shfl_xor_sync(0xFFFFFFFFu, s1i, o);
        s1j += __shfl_xor_sync(0xFFFFFFFFu, s1j, o);
    }

    if (lane == 0) {
        float s0 = 0.f;
        if (ti == tj) {
            if (!aii) s0 = s1i;
        } else {
            if (aji && !aii) s0 += s1i;
            if (aij && !ajj) s0 += s1j;
        }
        out[warp] = s + s0 + bxs[0];
    }
}

// ---------------------------------------------------------------------------
// pack: TWO rows per block, INTERLEAVED flat quad loop (no smem, no sync,
// no division) — R15 proven body. Reads the flagged-row bitmask AFTER
// cudaGridDependencySynchronize() (flag1 triggers post-store).
// Triggers PDL at block START (node_y2 PSS starts under pack's last wave).
// Bit layout: word = group*4 + k; bit 'lane' = column group*128 + lane*4 + k.
// ---------------------------------------------------------------------------
__global__ void pack_adj_kernel(const unsigned int* __restrict__ adj,
                                const unsigned* __restrict__ mask,
                                int n, int ngroups,
                                unsigned* __restrict__ bits) {
    cudaTriggerProgrammaticLaunchCompletion();
    cudaGridDependencySynchronize();   // flag1's mask writes now visible

    int row0 = blockIdx.x * 2;
    int row1 = row0 + 1;
    int f0 = (mask[row0 >> 5] >> (row0 & 31)) & 1u;
    int f1 = (row1 < n) ? ((mask[row1 >> 5] >> (row1 & 31)) & 1u) : 0;

    int ra = f0 ? row0 : row1;       // first flagged row
    int rb = row1;                   // second flagged row (only if cnt==2)
    int cnt = f0 + f1;
    if (cnt == 0) return;

    int warp = threadIdx.x >> 5;
    int lane = threadIdx.x & 31;
    int nquads = ngroups >> 2;       // 19 (groups 0..75 full)

    int total = cnt * nquads;
    for (int t = warp; t < total; t += 8) {
        int r = t >= nquads;
        int q = r ? (t - nquads) : t;
        int row = r ? rb : ra;
        const uint4* rowp4 = (const uint4*)(adj + (long)row * n);
        uint4* outp = (uint4*)(bits + (long)row * (ngroups * 4));

        int g0 = q * 4;
        uint4 v0 = __ldcs(&rowp4[(g0 + 0) * 32 + lane]);
        uint4 v1 = __ldcs(&rowp4[(g0 + 1) * 32 + lane]);
        uint4 v2 = __ldcs(&rowp4[(g0 + 2) * 32 + lane]);
        uint4 v3 = __ldcs(&rowp4[(g0 + 3) * 32 + lane]);

        unsigned a0 = __ballot_sync(0xFFFFFFFFu, v0.x != 0u);
        unsigned a1 = __ballot_sync(0xFFFFFFFFu, v0.y != 0u);
        unsigned a2 = __ballot_sync(0xFFFFFFFFu, v0.z != 0u);
        unsigned a3 = __ballot_sync(0xFFFFFFFFu, v0.w != 0u);
        unsigned b0 = __ballot_sync(0xFFFFFFFFu, v1.x != 0u);
        unsigned b1 = __ballot_sync(0xFFFFFFFFu, v1.y != 0u);
        unsigned b2 = __ballot_sync(0xFFFFFFFFu, v1.z != 0u);
        unsigned b3 = __ballot_sync(0xFFFFFFFFu, v1.w != 0u);
        unsigned c0 = __ballot_sync(0xFFFFFFFFu, v2.x != 0u);
        unsigned c1 = __ballot_sync(0xFFFFFFFFu, v2.y != 0u);
        unsigned c2 = __ballot_sync(0xFFFFFFFFu, v2.z != 0u);
        unsigned c3 = __ballot_sync(0xFFFFFFFFu, v2.w != 0u);
        unsigned d0 = __ballot_sync(0xFFFFFFFFu, v3.x != 0u);
        unsigned d1 = __ballot_sync(0xFFFFFFFFu, v3.y != 0u);
        unsigned d2 = __ballot_sync(0xFFFFFFFFu, v3.z != 0u);
        unsigned d3 = __ballot_sync(0xFFFFFFFFu, v3.w != 0u);

        if (lane == 0)      outp[g0]     = make_uint4(a0, a1, a2, a3);
        else if (lane == 1) outp[g0 + 1] = make_uint4(b0, b1, b2, b3);
        else if (lane == 2) outp[g0 + 2] = make_uint4(c0, c1, c2, c3);
        else if (lane == 3) outp[g0 + 3] = make_uint4(d0, d1, d2, d3);
    }

    // tail: groups 76..78 per flagged row, flat bounds-checked loop
    int ntail = ngroups - nquads * 4;          // 3
    int ttotal = cnt * ntail;
    for (int t = warp; t < ttotal; t += 8) {
        int r = t >= ntail;
        int gi = r ? (t - ntail) : t;
        int row = r ? rb : ra;
        const uint4* rowp4 = (const uint4*)(adj + (long)row * n);
        uint4* outp = (uint4*)(bits + (long)row * (ngroups * 4));
        int tg = nquads * 4 + gi;

        int col0 = tg * 128 + lane * 4;
        uint4 v = make_uint4(0u, 0u, 0u, 0u);
        if (col0 + 3 < n) {
            v = __ldcs(&rowp4[tg * 32 + lane]);
        } else if (col0 < n) {
            const unsigned* p = adj + (long)row * n + col0;
            v.x = p[0];
            if (col0 + 1 < n) v.y = p[1];
            if (col0 + 2 < n) v.z = p[2];
        }
        unsigned b0 = __ballot_sync(0xFFFFFFFFu, v.x != 0u);
        unsigned b1 = __ballot_sync(0xFFFFFFFFu, v.y != 0u);
        unsigned b2 = __ballot_sync(0xFFFFFFFFu, v.z != 0u);
        unsigned b3 = __ballot_sync(0xFFFFFFFFu, v.w != 0u);
        if (lane == 0)
            outp[tg] = make_uint4(b0, b1, b2, b3);
    }
}

// ---------------------------------------------------------------------------
// edge_cn: out[e] += sum_{n in cn1(e)} y2[n].  PLAIN launch (waits pack +
// node_y2). All 6 uint4 L2 loads front-batched (one L2 round-trip deep).
// ---------------------------------------------------------------------------
__global__ void edge_cn_kernel(const int* __restrict__ tar,   // [2, E]
                               int e_cnt, int ngroups,
                               const unsigned* __restrict__ bits,
                               const float* __restrict__ y2,
                               float* __restrict__ out) {
    int warp = (blockIdx.x * blockDim.x + threadIdx.x) >> 5;
    int lane = threadIdx.x & 31;
    if (warp >= e_cnt) return;

    int ti = tar[warp];
    int tj = tar[e_cnt + warp];
    int wpg = ngroups * 4;

    const uint4* A = (const uint4*)(bits + (long)ti * wpg);
    const uint4* B = (const uint4*)(bits + (long)tj * wpg);

    // Front-batched loads: slots g, g+32, g+64 (assumes ngroups <= 96).
    int g0 = lane, g1 = lane + 32, g2 = lane + 64;
    uint4 z = make_uint4(0u, 0u, 0u, 0u);
    uint4 a0 = z, b0 = z, a1 = z, b1 = z, a2 = z, b2 = z;
    if (g0 < ngroups) { a0 = A[g0]; b0 = B[g0]; }
    if (g1 < ngroups) { a1 = A[g1]; b1 = B[g1]; }
    if (g2 < ngroups) { a2 = A[g2]; b2 = B[g2]; }

    float s = 0.f;
    {
        unsigned m0 = a0.x & b0.x, m1 = a0.y & b0.y;
        unsigned m2 = a0.z & b0.z, m3 = a0.w & b0.w;
        int base = g0 * 128;
        while (m0) { int bb = __ffs(m0) - 1; m0 &= m0 - 1; s += y2[base + bb * 4 + 0]; }
        while (m1) { int bb = __ffs(m1) - 1; m1 &= m1 - 1; s += y2[base + bb * 4 + 1]; }
        while (m2) { int bb = __ffs(m2) - 1; m2 &= m2 - 1; s += y2[base + bb * 4 + 2]; }
        while (m3) { int bb = __ffs(m3) - 1; m3 &= m3 - 1; s += y2[base + bb * 4 + 3]; }
    }
    {
        unsigned m0 = a1.x & b1.x, m1 = a1.y & b1.y;
        unsigned m2 = a1.z & b1.z, m3 = a1.w & b1.w;
        int base = g1 * 128;
        while (m0) { int bb = __ffs(m0) - 1; m0 &= m0 - 1; s += y2[base + bb * 4 + 0]; }
        while (m1) { int bb = __ffs(m1) - 1; m1 &= m1 - 1; s += y2[base + bb * 4 + 1]; }
        while (m2) { int bb = __ffs(m2) - 1; m2 &= m2 - 1; s += y2[base + bb * 4 + 2]; }
        while (m3) { int bb = __ffs(m3) - 1; m3 &= m3 - 1; s += y2[base + bb * 4 + 3]; }
    }
    {
        unsigned m0 = a2.x & b2.x, m1 = a2.y & b2.y;
        unsigned m2 = a2.z & b2.z, m3 = a2.w & b2.w;
        int base = g2 * 128;
        while (m0) { int bb = __ffs(m0) - 1; m0 &= m0 - 1; s += y2[base + bb * 4 + 0]; }
        while (m1) { int bb = __ffs(m1) - 1; m1 &= m1 - 1; s += y2[base + bb * 4 + 1]; }
        while (m2) { int bb = __ffs(m2) - 1; m2 &= m2 - 1; s += y2[base + bb * 4 + 2]; }
        while (m3) { int bb = __ffs(m3) - 1; m3 &= m3 - 1; s += y2[base + bb * 4 + 3]; }
    }

#pragma unroll
    for (int o = 16; o; o >>= 1)
        s += __shfl_xor_sync(0xFFFFFFFFu, s, o);

    if (lane == 0 && s != 0.f)
        out[warp] += s;
}

// ---------------------------------------------------------------------------
// Launch
// Inputs (metadata order): x[N*D] f32, adj01[N*N], adj1[N*N], tar_ei[2*E] i32,
//                          Wxs[1*3D] f32, bxs[1] f32, NCN_mode i32 (==0)
// Output: [E, 1] f32
// Stream/PDL order:
//   edge_dot (plain, trigger@start)
//   -> flag1  (PSS: starts immediately, concurrent with edge_dot;
//              triggers at END after mask stores)
//   -> pack   (PSS + gridDepSync before reading mask; trigger@start)
//   -> node_y2(PSS: starts under pack's last wave)
//   -> edge_cn(plain: waits pack + node_y2 completion)
// ---------------------------------------------------------------------------
extern "C" void kernel_launch(void* const* d_in, const int* in_sizes, int n_in,
                              void* d_out, int out_size) {
    const float*        x    = (const float*)d_in[0];
    const unsigned int* adj1 = (const unsigned int*)d_in[2];  // bool as 4-byte words
    const int*          tar  = (const int*)d_in[3];
    const float*        Wxs  = (const float*)d_in[4];
    const float*        bxs  = (const float*)d_in[5];
    float*              out  = (float*)d_out;

    const int N = in_sizes[0] / DIM;            // 10000
    const int E = in_sizes[3] / 2;              // 8192
    const int NGRP = (N + 127) / 128;           // 79
    const int NWORDS = (N + 31) / 32;           // 313

    unsigned* bits;
    float* y2;
    unsigned* mask;
    cudaGetSymbolAddress((void**)&bits, g_bits32);
    cudaGetSymbolAddress((void**)&y2, g_y2);
    cudaGetSymbolAddress((void**)&mask, g_mask);

    cudaLaunchAttribute pss[1];
    pss[0].id = cudaLaunchAttributeProgrammaticStreamSerialization;
    pss[0].val.programmaticStreamSerializationAllowed = 1;

    // edge_dot first: no dependencies, triggers at start
    edge_dot_kernel<<<(E + 7) / 8, 256>>>(x, tar, Wxs, bxs, adj1, N, E, out);

    // flag1: PSS -> starts immediately, concurrent with edge_dot
    {
        cudaLaunchConfig_t cfg = {};
        cfg.gridDim  = dim3(1);
        cfg.blockDim = dim3(1024);
        cfg.attrs = pss;
        cfg.numAttrs = 1;
        cudaLaunchKernelEx(&cfg, flag1_kernel, tar, 2 * E,
                           (unsigned*)mask, NWORDS);
    }

    // pack: PSS after flag1 (trigger@flag1-end) + gridDepSync inside
    {
        cudaLaunchConfig_t cfg = {};
        cfg.gridDim  = dim3((unsigned)((N + 1) / 2));
        cfg.blockDim = dim3(256);
        cfg.attrs = pss;
        cfg.numAttrs = 1;
        cudaLaunchKernelEx(&cfg, pack_adj_kernel, adj1,
                           (const unsigned*)mask, N, NGRP, (unsigned*)bits);
    }

    // node_y2: PSS after pack (pack triggers at block start) -> executes
    // under pack's last wave; finishes before pack completes.
    {
        cudaLaunchConfig_t cfg = {};
        cfg.gridDim  = dim3((N + 7) / 8);
        cfg.blockDim = dim3(256);
        cfg.attrs = pss;
        cfg.numAttrs = 1;
        cudaLaunchKernelEx(&cfg, node_y2_kernel, x, Wxs, N, y2);
    }

    // edge_cn: plain launch -> waits for pack + node_y2 completion
    edge_cn_kernel<<<(E + 7) / 8, 256>>>(tar, E, NGRP, bits, y2, out);

    (void)n_in; (void)out_size;
}